// round 13
// baseline (speedup 1.0000x reference)
#include <cuda_runtime.h>
#include <cuda_bf16.h>
#include <math.h>
#include <stdint.h>

#define SQ 512
#define HID 768
#define NHEAD 12
#define DHEAD 64
#define BATCH 8
#define NLAYER 12
#define FFDIM 3072
#define ROWS (BATCH*SQ)
#define BHT (BATCH*NHEAD)
#define HD (SQ*DHEAD)

#define WSZ (HID*HID)
#define WISZ (HID*FFDIM)
#define LOFF (4*WSZ + 2*WISZ)

/* ------------------------- scratch (device globals) ---------------------- */
__device__ float g_x[ROWS*HID];
__device__ float g_h1[ROWS*HID];
__device__ float g_tmp[ROWS*HID];
__device__ __nv_bfloat16 g_xh[ROWS*HID],  g_xl[ROWS*HID];
__device__ __nv_bfloat16 g_h1h[ROWS*HID], g_h1l[ROWS*HID];
__device__ __nv_bfloat16 g_qkvh[(size_t)3*ROWS*HID], g_qkvl[(size_t)3*ROWS*HID];
__device__ __nv_bfloat16 g_ctxh[ROWS*HID],g_ctxl[ROWS*HID];
__device__ __nv_bfloat16 g_ffh[(size_t)ROWS*FFDIM], g_ffl[(size_t)ROWS*FFDIM];
__device__ __nv_bfloat16 g_pqkh[2*NHEAD*HD], g_pqkl[2*NHEAD*HD];
__device__ __nv_bfloat16 g_relh[SQ*HID],  g_rell[SQ*HID];
__device__ __nv_bfloat16 g_wth[(size_t)NLAYER*LOFF];
__device__ __nv_bfloat16 g_wtl[(size_t)NLAYER*LOFF];
__device__ float g_qkvb[NLAYER*2304];
__device__ float g_sc[(size_t)BHT*SQ*SQ];
__device__ float g_c2p[(size_t)BHT*SQ*SQ];
__device__ float g_p2c[(size_t)BHT*SQ*SQ];
__device__ float g_p2cg[(size_t)BHT*SQ*SQ];
__device__ __nv_bfloat16 g_ph[(size_t)BHT*SQ*SQ], g_pl[(size_t)BHT*SQ*SQ];
__device__ int g_cidx[1023], g_pidx[1023];

/* ------------------------- PTX helpers ----------------------------------- */
__device__ __forceinline__ uint32_t smem_u32(const void* p) {
    uint32_t a;
    asm("{ .reg .u64 t; cvta.to.shared.u64 t, %1; cvt.u32.u64 %0, t; }" : "=r"(a) : "l"(p));
    return a;
}
#define SWZ(x) ((x) ^ (((x) >> 3) & 0x70))

#define CPA16(dst, src) asm volatile("cp.async.cg.shared.global [%0], [%1], 16;" :: "r"(dst), "l"(src))
#define CPA_COMMIT() asm volatile("cp.async.commit_group;" ::: "memory")
#define CPA_WAIT1() asm volatile("cp.async.wait_group 1;" ::: "memory")
#define CPA_WAIT0() asm volatile("cp.async.wait_group 0;" ::: "memory")

__device__ __forceinline__ void ldm4(uint32_t* r, uint32_t addr) {
    asm volatile("ldmatrix.sync.aligned.m8n8.x4.shared.b16 {%0,%1,%2,%3}, [%4];"
        : "=r"(r[0]), "=r"(r[1]), "=r"(r[2]), "=r"(r[3]) : "r"(addr));
}
__device__ __forceinline__ void mma16816(float* c, const uint32_t* a, uint32_t b0, uint32_t b1) {
    asm volatile("mma.sync.aligned.m16n8k16.row.col.f32.bf16.bf16.f32 "
        "{%0,%1,%2,%3}, {%4,%5,%6,%7}, {%8,%9}, {%0,%1,%2,%3};"
        : "+f"(c[0]), "+f"(c[1]), "+f"(c[2]), "+f"(c[3])
        : "r"(a[0]), "r"(a[1]), "r"(a[2]), "r"(a[3]), "r"(b0), "r"(b1));
}
__device__ __forceinline__ uint32_t amat_addr(uint32_t base, int mbase, int ks, int lane) {
    int mat = lane >> 3, rin = lane & 7;
    int m = mbase + rin + ((mat & 1) << 3);
    int quad = 2 * ks + (mat >> 1);
    return base + SWZ(m * 128 + quad * 16);
}
__device__ __forceinline__ uint32_t bmat_addr(uint32_t base, int nbase, int ks, int lane) {
    int mat = lane >> 3, rin = lane & 7;
    int n = nbase + rin + ((mat >> 1) << 3);
    int quad = 2 * ks + (mat & 1);
    return base + SWZ(n * 128 + quad * 16);
}

/* ------------------------- rel-pos bucket tables -------------------------- */
__device__ __forceinline__ int log_bucket(int rel) {
    const int mid = 128;
    float abs_pos;
    if (rel < mid && rel > -mid) abs_pos = (float)(mid - 1);
    else                         abs_pos = fabsf((float)rel);
    if (abs_pos <= (float)mid) return rel;
    float denom = (float)log(511.0 / 128.0);
    float log_pos = ceilf(logf(abs_pos / 128.0f) / denom * 127.0f) + 128.0f;
    float sgn = (rel > 0) ? 1.0f : ((rel < 0) ? -1.0f : 0.0f);
    return (int)(log_pos * sgn);
}
__global__ void build_tables_kernel() {
    int i = blockIdx.x * blockDim.x + threadIdx.x;
    if (i >= 1023) return;
    int d = i - 511;
    int c = log_bucket(d) + 256;  c = min(max(c, 0), 511);
    int p = 256 - log_bucket(-d); p = min(max(p, 0), 511);
    g_cidx[i] = c; g_pidx[i] = p;
}

__device__ __forceinline__ void split1(float v, __nv_bfloat16& h, __nv_bfloat16& l) {
    h = __float2bfloat16(v);
    l = __float2bfloat16(v - __bfloat162float(h));
}

/* staged concat bias [L][2304] = [bq|bk|bv] */
__global__ void qkvbias_kernel(const float* __restrict__ bq, const float* __restrict__ bk,
                               const float* __restrict__ bv, float* __restrict__ out) {
    int i = blockIdx.x * blockDim.x + threadIdx.x;
    if (i >= NLAYER * 2304) return;
    int l = i / 2304, j = i - l * 2304;
    float v;
    if (j < 768)       v = bq[l * 768 + j];
    else if (j < 1536) v = bk[l * 768 + j - 768];
    else               v = bv[l * 768 + j - 1536];
    out[i] = v;
}

/* transpose + hi/lo split: dst[n*K+k] = split(src[k*N+n]) */
__global__ void wsplit_kernel(const float* __restrict__ src, __nv_bfloat16* __restrict__ dh,
                              __nv_bfloat16* __restrict__ dl, int K, int N,
                              long long sStride, long long dStride) {
    __shared__ float t[32][33];
    int l = blockIdx.z;
    const float* s = src + (size_t)l * sStride;
    __nv_bfloat16* oh = dh + (size_t)l * dStride;
    __nv_bfloat16* ol = dl + (size_t)l * dStride;
    int k0 = blockIdx.x * 32, n0 = blockIdx.y * 32;
    int tx = threadIdx.x, ty = threadIdx.y;
#pragma unroll
    for (int i = 0; i < 32; i += 8) t[ty + i][tx] = s[(size_t)(k0 + ty + i) * N + n0 + tx];
    __syncthreads();
#pragma unroll
    for (int i = 0; i < 32; i += 8) {
        float v = t[tx][ty + i];
        __nv_bfloat16 h, lo; split1(v, h, lo);
        size_t o = (size_t)(n0 + ty + i) * K + k0 + tx;
        oh[o] = h; ol[o] = lo;
    }
}

__global__ void split_kernel(const float* __restrict__ s, __nv_bfloat16* __restrict__ oh,
                             __nv_bfloat16* __restrict__ ol, int n) {
    int i = blockIdx.x * blockDim.x + threadIdx.x;
    if (i < n) { __nv_bfloat16 h, l; split1(s[i], h, l); oh[i] = h; ol[i] = l; }
}

/* ------------------------- embedding + masked LN -------------------------- */
__global__ void embed_kernel(const float* __restrict__ we, const float* __restrict__ pe,
                             const float* __restrict__ lg, const float* __restrict__ lb,
                             const int* __restrict__ ids, const int* __restrict__ am,
                             float* __restrict__ out, __nv_bfloat16* __restrict__ outh,
                             __nv_bfloat16* __restrict__ outl) {
    __shared__ float red[256];
    int row = blockIdx.x, tid = threadIdx.x;
    int s = row & (SQ - 1);
    int id = ids[row];
    float v[3];
#pragma unroll
    for (int i = 0; i < 3; i++) {
        int c = tid + i * 256;
        v[i] = we[(size_t)id * HID + c] + pe[(size_t)s * HID + c];
    }
    float sum = v[0] + v[1] + v[2];
    red[tid] = sum; __syncthreads();
    for (int st = 128; st > 0; st >>= 1) { if (tid < st) red[tid] += red[tid + st]; __syncthreads(); }
    float mu = red[0] * (1.0f / HID); __syncthreads();
    float s2 = 0.f;
#pragma unroll
    for (int i = 0; i < 3; i++) { float d = v[i] - mu; s2 += d * d; }
    red[tid] = s2; __syncthreads();
    for (int st = 128; st > 0; st >>= 1) { if (tid < st) red[tid] += red[tid + st]; __syncthreads(); }
    float r = rsqrtf(red[0] * (1.0f / HID) + 1e-7f);
    float mf = (float)am[row];
    size_t rb = (size_t)row * HID;
#pragma unroll
    for (int i = 0; i < 3; i++) {
        int c = tid + i * 256;
        float o = ((v[i] - mu) * r * lg[c] + lb[c]) * mf;
        out[rb + c] = o;
        __nv_bfloat16 h, l; split1(o, h, l);
        outh[rb + c] = h; outl[rb + c] = l;
    }
}

/* ------------------------- layernorm (+ optional hi/lo) ------------------- */
__global__ void ln_kernel(const float* __restrict__ in, const float* __restrict__ lg,
                          const float* __restrict__ lb, float* __restrict__ out,
                          __nv_bfloat16* __restrict__ outh, __nv_bfloat16* __restrict__ outl) {
    __shared__ float red[256];
    int row = blockIdx.x, tid = threadIdx.x;
    const float* xr = in + (size_t)row * HID;
    float v[3];
#pragma unroll
    for (int i = 0; i < 3; i++) v[i] = xr[tid + i * 256];
    float sum = v[0] + v[1] + v[2];
    red[tid] = sum; __syncthreads();
    for (int st = 128; st > 0; st >>= 1) { if (tid < st) red[tid] += red[tid + st]; __syncthreads(); }
    float mu = red[0] * (1.0f / HID); __syncthreads();
    float s2 = 0.f;
#pragma unroll
    for (int i = 0; i < 3; i++) { float d = v[i] - mu; s2 += d * d; }
    red[tid] = s2; __syncthreads();
    for (int st = 128; st > 0; st >>= 1) { if (tid < st) red[tid] += red[tid + st]; __syncthreads(); }
    float r = rsqrtf(red[0] * (1.0f / HID) + 1e-7f);
    size_t rb = (size_t)row * HID;
#pragma unroll
    for (int i = 0; i < 3; i++) {
        int c = tid + i * 256;
        float o = (v[i] - mu) * r * lg[c] + lb[c];
        out[rb + c] = o;
        if (outh) { __nv_bfloat16 h, l; split1(o, h, l); outh[rb + c] = h; outl[rb + c] = l; }
    }
}

/* ------------------------- p2c transpose-gather --------------------------- */
__global__ void p2cg_kernel(const float* __restrict__ p2c, float* __restrict__ p2cg) {
    __shared__ float t[32][33];
    int bh = blockIdx.z;
    int k0 = blockIdx.x * 32, q0 = blockIdx.y * 32;
    const float* src = p2c + (size_t)bh * SQ * SQ;
    float* dst = p2cg + (size_t)bh * SQ * SQ;
    int tx = threadIdx.x, ty = threadIdx.y;
#pragma unroll
    for (int i = 0; i < 32; i += 8) {
        int k = k0 + ty + i;
        int q = q0 + tx;
        t[ty + i][tx] = src[(size_t)k * SQ + g_pidx[q - k + 511]];
    }
    __syncthreads();
#pragma unroll
    for (int i = 0; i < 32; i += 8)
        dst[(size_t)(q0 + ty + i) * SQ + k0 + tx] = t[tx][ty + i];
}

/* ------------------------- softmax (contiguous reads -> bf16 hi/lo) ------- */
__global__ void attn_softmax_kernel(const float* __restrict__ sc, const float* __restrict__ c2p,
                                    const float* __restrict__ p2cg, const int* __restrict__ am,
                                    __nv_bfloat16* __restrict__ ph, __nv_bfloat16* __restrict__ pl) {
    int q = blockIdx.x, bh = blockIdx.y;
    int b = bh / NHEAD;
    const float inv_scale = 0.07216878364870322f;
    const float* row  = sc   + ((size_t)bh * SQ + q) * SQ;
    const float* crow = c2p  + ((size_t)bh * SQ + q) * SQ;
    const float* prow = p2cg + ((size_t)bh * SQ + q) * SQ;
    int tid = threadIdx.x;
    bool mq = am[b * SQ + q] != 0;

    float v[2]; bool ok[2];
    float lmax = -3.402823466e38f;
#pragma unroll
    for (int i = 0; i < 2; i++) {
        int k = tid + i * 256;
        int di = q - k + 511;
        float s = (row[k] + crow[g_cidx[di]] + prow[k]) * inv_scale;
        ok[i] = mq && (am[b * SQ + k] != 0);
        v[i] = ok[i] ? s : -3.402823466e38f;
        lmax = fmaxf(lmax, v[i]);
    }
    __shared__ float red[256];
    red[tid] = lmax; __syncthreads();
    for (int st = 128; st > 0; st >>= 1) { if (tid < st) red[tid] = fmaxf(red[tid], red[tid + st]); __syncthreads(); }
    float m = red[0]; __syncthreads();
    float ls = 0.f;
#pragma unroll
    for (int i = 0; i < 2; i++) { float e = expf(v[i] - m); v[i] = e; ls += e; }
    red[tid] = ls; __syncthreads();
    for (int st = 128; st > 0; st >>= 1) { if (tid < st) red[tid] += red[tid + st]; __syncthreads(); }
    float inv = 1.0f / red[0];
    size_t ob = ((size_t)bh * SQ + q) * SQ;
#pragma unroll
    for (int i = 0; i < 2; i++) {
        int k = tid + i * 256;
        float p = ok[i] ? v[i] * inv : 0.0f;
        __nv_bfloat16 h, l; split1(p, h, l);
        ph[ob + k] = h; pl[ob + k] = l;
    }
}

/* ------------------------- mma.sync split-bf16 GEMM ----------------------- */
#define KC 64
#define ABYTES 16384
#define A2BYTES 32768

#define FL_GELU 1
#define FL_RES  2
#define FL_F32  4
#define FL_HILO 8
#define FL_QKV  64
#define FL_PQK  128

__device__ __forceinline__ void epi_pair(
    float v0, float v1, int m, int n,
    const float* bias, const float* Rb, float* Cf,
    __nv_bfloat16* Chi, __nv_bfloat16* Clo,
    int ldc, int ldh, size_t cfoff, size_t hoff, int flags)
{
    if (bias) { v0 += __ldg(bias + n); v1 += __ldg(bias + n + 1); }
    if (flags & FL_RES) {
        float2 rv = *reinterpret_cast<const float2*>(Rb + (size_t)m * ldc + n);
        v0 += rv.x; v1 += rv.y;
    }
    if (flags & FL_GELU) {
        v0 = 0.5f * v0 * (1.0f + erff(v0 * 0.70710678118654752f));
        v1 = 0.5f * v1 * (1.0f + erff(v1 * 0.70710678118654752f));
    }
    if (flags & FL_F32) {
        float2* p = reinterpret_cast<float2*>(Cf + cfoff + (size_t)m * ldc + n);
        *p = make_float2(v0, v1);
    }
    if (flags & FL_QKV) {
        int r = n / 768, nr = n - r * 768;
        __nv_bfloat16 h0, l0, h1, l1;
        split1(v0, h0, l0); split1(v1, h1, l1);
        if (r < 2) {
            size_t base = (size_t)r * ((size_t)ROWS * HID)
                        + (size_t)(m >> 9) * ((size_t)NHEAD * HD) + (size_t)(nr >> 6) * HD
                        + (size_t)(m & 511) * 64 + (nr & 63);
            __nv_bfloat162 hh; hh.x = h0; hh.y = h1;
            __nv_bfloat162 ll; ll.x = l0; ll.y = l1;
            *reinterpret_cast<uint32_t*>(Chi + base) = *reinterpret_cast<uint32_t*>(&hh);
            *reinterpret_cast<uint32_t*>(Clo + base) = *reinterpret_cast<uint32_t*>(&ll);
        } else {
            size_t vb = (size_t)2 * ((size_t)ROWS * HID);
            size_t i0 = vb + ((size_t)(m >> 9) * NHEAD + (nr >> 6)) * ((size_t)64 * SQ)
                      + (size_t)(nr & 63) * SQ + (m & 511);
            size_t i1 = vb + ((size_t)(m >> 9) * NHEAD + ((nr + 1) >> 6)) * ((size_t)64 * SQ)
                      + (size_t)((nr + 1) & 63) * SQ + (m & 511);
            Chi[i0] = h0; Clo[i0] = l0;
            Chi[i1] = h1; Clo[i1] = l1;
        }
        return;
    }
    if (flags & FL_PQK) {
        int r = n / 768, nr = n - r * 768;
        size_t base = (size_t)r * ((size_t)NHEAD * HD) + (size_t)(nr >> 6) * HD
                    + (size_t)m * 64 + (nr & 63);
        __nv_bfloat16 h0, l0, h1, l1;
        split1(v0, h0, l0); split1(v1, h1, l1);
        __nv_bfloat162 hh; hh.x = h0; hh.y = h1;
        __nv_bfloat162 ll; ll.x = l0; ll.y = l1;
        *reinterpret_cast<uint32_t*>(Chi + base) = *reinterpret_cast<uint32_t*>(&hh);
        *reinterpret_cast<uint32_t*>(Clo + base) = *reinterpret_cast<uint32_t*>(&ll);
        return;
    }
    if (flags & FL_HILO) {
        size_t base = hoff + (size_t)m * ldh + n;
        __nv_bfloat16 h0, l0, h1, l1;
        split1(v0, h0, l0); split1(v1, h1, l1);
        __nv_bfloat162 hh; hh.x = h0; hh.y = h1;
        __nv_bfloat162 ll; ll.x = l0; ll.y = l1;
        *reinterpret_cast<uint32_t*>(Chi + base) = *reinterpret_cast<uint32_t*>(&hh);
        *reinterpret_cast<uint32_t*>(Clo + base) = *reinterpret_cast<uint32_t*>(&ll);
    }
}

template<int TN>
__device__ __forceinline__ void load_chunk(
    uint32_t sst, const __nv_bfloat16* Azh, const __nv_bfloat16* Azl,
    const __nv_bfloat16* Bzh, const __nv_bfloat16* Bzl,
    int m0, int n0, int k0, int lda, int ldb, int tid)
{
    const uint32_t oAl = ABYTES, oBh = 2 * ABYTES, oBl = 2 * ABYTES + TN * 128;
#pragma unroll
    for (int i = 0; i < 4; i++) {
        int q = tid + i * 256;
        int row = q >> 3, quad = q & 7;
        size_t goff = (size_t)(m0 + row) * lda + k0 + quad * 8;
        uint32_t so = SWZ(row * 128 + quad * 16);
        CPA16(sst + so, Azh + goff);
        CPA16(sst + oAl + so, Azl + goff);
    }
#pragma unroll
    for (int i = 0; i < TN / 32; i++) {
        int q = tid + i * 256;
        int row = q >> 3, quad = q & 7;
        size_t goff = (size_t)(n0 + row) * ldb + k0 + quad * 8;
        uint32_t so = SWZ(row * 128 + quad * 16);
        CPA16(sst + oBh + so, Bzh + goff);
        CPA16(sst + oBl + so, Bzl + goff);
    }
    CPA_COMMIT();
}

template<int TN>
__global__ __launch_bounds__(256, (TN == 64) ? 2 : 1)
void hmma_kernel(const __nv_bfloat16* __restrict__ Ah, const __nv_bfloat16* __restrict__ Al,
                 const __nv_bfloat16* __restrict__ Bh, const __nv_bfloat16* __restrict__ Bl,
                 const float* __restrict__ bias, const float* __restrict__ Rb,
                 float* __restrict__ Cf, __nv_bfloat16* __restrict__ Chi, __nv_bfloat16* __restrict__ Clo,
                 int K, int lda, int ldb, int ldc, int ldh,
                 long long sAb, long long sAh_, long long sBb, long long sBh_,
                 long long sCb, long long sCh_, long long sHb, long long sHh_,
                 int nh, int flags)
{
    extern __shared__ char smem[];
    const int STAGE = 2 * ABYTES + 2 * TN * 128;
    uint32_t sb = smem_u32(smem);

    int tid = threadIdx.x, wid = tid >> 5, lane = tid & 31;
    int z = blockIdx.z, bo = z / nh, ho = z - bo * nh;
    int m0 = blockIdx.y * 128, n0 = blockIdx.x * TN;

    const __nv_bfloat16* Azh = Ah + (size_t)bo * sAb + (size_t)ho * sAh_;
    const __nv_bfloat16* Azl = Al + (size_t)bo * sAb + (size_t)ho * sAh_;
    const __nv_bfloat16* Bzh = Bh + (size_t)bo * sBb + (size_t)ho * sBh_;
    const __nv_bfloat16* Bzl = Bl + (size_t)bo * sBb + (size_t)ho * sBh_;

    const int MI = (TN == 128) ? 2 : 1;
    int wm = (TN == 128) ? (wid & 3) * 32 : wid * 16;
    int wn = (TN == 128) ? (wid >> 2) * 64 : 0;

    float acc[(TN == 128) ? 2 : 1][8][4];
#pragma unroll
    for (int a = 0; a < MI; a++)
#pragma unroll
        for (int b = 0; b < 8; b++)
#pragma unroll
            for (int c = 0; c < 4; c++) acc[a][b][c] = 0.f;

    int nch = K / KC;
    load_chunk<TN>(sb, Azh, Azl, Bzh, Bzl, m0, n0, 0, lda, ldb, tid);

    for (int ch = 0; ch < nch; ch++) {
        if (ch + 1 < nch) {
            load_chunk<TN>(sb + ((ch + 1) & 1) * STAGE, Azh, Azl, Bzh, Bzl,
                           m0, n0, (ch + 1) * KC, lda, ldb, tid);
            CPA_WAIT1();
        } else {
            CPA_WAIT0();
        }
        __syncthreads();

        uint32_t st = sb + (ch & 1) * STAGE;
        const uint32_t oAl = ABYTES, oBh = 2 * ABYTES, oBl = 2 * ABYTES + TN * 128;
#pragma unroll
        for (int ks = 0; ks < 4; ks++) {
            uint32_t ah[MI][4], al[MI][4];
#pragma unroll
            for (int mi = 0; mi < MI; mi++) {
                ldm4(ah[mi], amat_addr(st, wm + mi * 16, ks, lane));
                ldm4(al[mi], amat_addr(st + oAl, wm + mi * 16, ks, lane));
            }
#pragma unroll
            for (int ngp = 0; ngp < 4; ngp += 2) {
                uint32_t b0h[4], b1h[4], b0l[4], b1l[4];
                ldm4(b0h, bmat_addr(st + oBh, wn + ngp * 16, ks, lane));
                ldm4(b1h, bmat_addr(st + oBh, wn + (ngp + 1) * 16, ks, lane));
                ldm4(b0l, bmat_addr(st + oBl, wn + ngp * 16, ks, lane));
                ldm4(b1l, bmat_addr(st + oBl, wn + (ngp + 1) * 16, ks, lane));
#pragma unroll
                for (int mi = 0; mi < MI; mi++) {
                    mma16816(acc[mi][2 * ngp],     ah[mi], b0h[0], b0h[1]);
                    mma16816(acc[mi][2 * ngp + 1], ah[mi], b0h[2], b0h[3]);
                    mma16816(acc[mi][2 * ngp + 2], ah[mi], b1h[0], b1h[1]);
                    mma16816(acc[mi][2 * ngp + 3], ah[mi], b1h[2], b1h[3]);
                }
#pragma unroll
                for (int mi = 0; mi < MI; mi++) {
                    mma16816(acc[mi][2 * ngp],     ah[mi], b0l[0], b0l[1]);
                    mma16816(acc[mi][2 * ngp + 1], ah[mi], b0l[2], b0l[3]);
                    mma16816(acc[mi][2 * ngp + 2], ah[mi], b1l[0], b1l[1]);
                    mma16816(acc[mi][2 * ngp + 3], ah[mi], b1l[2], b1l[3]);
                }
#pragma unroll
                for (int mi = 0; mi < MI; mi++) {
                    mma16816(acc[mi][2 * ngp],     al[mi], b0h[0], b0h[1]);
                    mma16816(acc[mi][2 * ngp + 1], al[mi], b0h[2], b0h[3]);
                    mma16816(acc[mi][2 * ngp + 2], al[mi], b1h[0], b1h[1]);
                    mma16816(acc[mi][2 * ngp + 3], al[mi], b1h[2], b1h[3]);
                }
            }
        }
        __syncthreads();
    }

    size_t cfoff = (size_t)bo * sCb + (size_t)ho * sCh_;
    size_t hoff  = (size_t)bo * sHb + (size_t)ho * sHh_;
    int r0 = lane >> 2, cc = (lane & 3) * 2;
#pragma unroll
    for (int mi = 0; mi < MI; mi++) {
#pragma unroll
        for (int nf = 0; nf < 8; nf++) {
            int m_ = m0 + wm + mi * 16 + r0;
            int n_ = n0 + wn + nf * 8 + cc;
            epi_pair(acc[mi][nf][0], acc[mi][nf][1], m_,     n_, bias, Rb, Cf, Chi, Clo, ldc, ldh, cfoff, hoff, flags);
            epi_pair(acc[mi][nf][2], acc[mi][nf][3], m_ + 8, n_, bias, Rb, Cf, Chi, Clo, ldc, ldh, cfoff, hoff, flags);
        }
    }
}

/* --------- TM=256 x TN=128 variant (big-N GEMMs): ratio-6 mma:ldsm -------- */
#define STAGE256 (2 * A2BYTES + 2 * 128 * 128)   /* 96 KB */

__device__ __forceinline__ void load_chunk256(
    uint32_t sst, const __nv_bfloat16* Azh, const __nv_bfloat16* Azl,
    const __nv_bfloat16* Bzh, const __nv_bfloat16* Bzl,
    int m0, int n0, int k0, int lda, int ldb, int tid)
{
    const uint32_t oAl = A2BYTES, oBh = 2 * A2BYTES, oBl = 2 * A2BYTES + 16384;
#pragma unroll
    for (int i = 0; i < 8; i++) {
        int q = tid + i * 256;
        int row = q >> 3, quad = q & 7;
        size_t goff = (size_t)(m0 + row) * lda + k0 + quad * 8;
        uint32_t so = SWZ(row * 128 + quad * 16);
        CPA16(sst + so, Azh + goff);
        CPA16(sst + oAl + so, Azl + goff);
    }
#pragma unroll
    for (int i = 0; i < 4; i++) {
        int q = tid + i * 256;
        int row = q >> 3, quad = q & 7;
        size_t goff = (size_t)(n0 + row) * ldb + k0 + quad * 8;
        uint32_t so = SWZ(row * 128 + quad * 16);
        CPA16(sst + oBh + so, Bzh + goff);
        CPA16(sst + oBl + so, Bzl + goff);
    }
    CPA_COMMIT();
}

__global__ __launch_bounds__(256, 1)
void hmma256_kernel(const __nv_bfloat16* __restrict__ Ah, const __nv_bfloat16* __restrict__ Al,
                    const __nv_bfloat16* __restrict__ Bh, const __nv_bfloat16* __restrict__ Bl,
                    const float* __restrict__ bias,
                    __nv_bfloat16* __restrict__ Chi, __nv_bfloat16* __restrict__ Clo,
                    int K, int lda, int ldb, int ldh, int flags)
{
    extern __shared__ char smem[];
    uint32_t sb = smem_u32(smem);

    int tid = threadIdx.x, wid = tid >> 5, lane = tid & 31;
    int m0 = blockIdx.y * 256, n0 = blockIdx.x * 128;

    int wm = (wid & 3) * 64;
    int wn = (wid >> 2) * 64;

    float acc[4][8][4];
#pragma unroll
    for (int a = 0; a < 4; a++)
#pragma unroll
        for (int b = 0; b < 8; b++)
#pragma unroll
            for (int c = 0; c < 4; c++) acc[a][b][c] = 0.f;

    int nch = K / KC;
    load_chunk256(sb, Ah, Al, Bh, Bl, m0, n0, 0, lda, ldb, tid);

    for (int ch = 0; ch < nch; ch++) {
        if (ch + 1 < nch) {
            load_chunk256(sb + ((ch + 1) & 1) * STAGE256, Ah, Al, Bh, Bl,
                          m0, n0, (ch + 1) * KC, lda, ldb, tid);
            CPA_WAIT1();
        } else {
            CPA_WAIT0();
        }
        __syncthreads();

        uint32_t st = sb + (ch & 1) * STAGE256;
        const uint32_t oAl = A2BYTES, oBh = 2 * A2BYTES, oBl = 2 * A2BYTES + 16384;
#pragma unroll
        for (int ks = 0; ks < 4; ks++) {
            uint32_t ah[4][4], al[4][4];
#pragma unroll
            for (int mi = 0; mi < 4; mi++) {
                ldm4(ah[mi], amat_addr(st, wm + mi * 16, ks, lane));
                ldm4(al[mi], amat_addr(st + oAl, wm + mi * 16, ks, lane));
            }
#pragma unroll
            for (int ngp = 0; ngp < 4; ngp += 2) {
                uint32_t b0h[4], b1h[4], b0l[4], b1l[4];
                ldm4(b0h, bmat_addr(st + oBh, wn + ngp * 16, ks, lane));
                ldm4(b1h, bmat_addr(st + oBh, wn + (ngp + 1) * 16, ks, lane));
                ldm4(b0l, bmat_addr(st + oBl, wn + ngp * 16, ks, lane));
                ldm4(b1l, bmat_addr(st + oBl, wn + (ngp + 1) * 16, ks, lane));
#pragma unroll
                for (int mi = 0; mi < 4; mi++) {
                    mma16816(acc[mi][2 * ngp],     ah[mi], b0h[0], b0h[1]);
                    mma16816(acc[mi][2 * ngp + 1], ah[mi], b0h[2], b0h[3]);
                    mma16816(acc[mi][2 * ngp + 2], ah[mi], b1h[0], b1h[1]);
                    mma16816(acc[mi][2 * ngp + 3], ah[mi], b1h[2], b1h[3]);
                }
#pragma unroll
                for (int mi = 0; mi < 4; mi++) {
                    mma16816(acc[mi][2 * ngp],     ah[mi], b0l[0], b0l[1]);
                    mma16816(acc[mi][2 * ngp + 1], ah[mi], b0l[2], b0l[3]);
                    mma16816(acc[mi][2 * ngp + 2], ah[mi], b1l[0], b1l[1]);
                    mma16816(acc[mi][2 * ngp + 3], ah[mi], b1l[2], b1l[3]);
                }
#pragma unroll
                for (int mi = 0; mi < 4; mi++) {
                    mma16816(acc[mi][2 * ngp],     al[mi], b0h[0], b0h[1]);
                    mma16816(acc[mi][2 * ngp + 1], al[mi], b0h[2], b0h[3]);
                    mma16816(acc[mi][2 * ngp + 2], al[mi], b1h[0], b1h[1]);
                    mma16816(acc[mi][2 * ngp + 3], al[mi], b1h[2], b1h[3]);
                }
            }
        }
        __syncthreads();
    }

    int r0 = lane >> 2, cc = (lane & 3) * 2;
#pragma unroll
    for (int mi = 0; mi < 4; mi++) {
#pragma unroll
        for (int nf = 0; nf < 8; nf++) {
            int m_ = m0 + wm + mi * 16 + r0;
            int n_ = n0 + wn + nf * 8 + cc;
            epi_pair(acc[mi][nf][0], acc[mi][nf][1], m_,     n_, bias, nullptr, nullptr, Chi, Clo, 0, ldh, 0, 0, flags);
            epi_pair(acc[mi][nf][2], acc[mi][nf][3], m_ + 8, n_, bias, nullptr, nullptr, Chi, Clo, 0, ldh, 0, 0, flags);
        }
    }
}

/* ------------------------- host-side GEMM wrapper ------------------------- */
#define STAGE64 (2 * ABYTES + 2 * 64 * 128)

static void tmma(const __nv_bfloat16* Ah, const __nv_bfloat16* Al,
                 const __nv_bfloat16* Bh, const __nv_bfloat16* Bl,
                 const float* bias, const float* Rb,
                 float* Cf, __nv_bfloat16* Chi, __nv_bfloat16* Clo,
                 int M, int N, int K, int lda, int ldb, int ldc, int ldh,
                 long long sAb, long long sAh, long long sBb, long long sBh,
                 long long sCb, long long sCh, long long sHb, long long sHh,
                 int nh, int nz, int flags)
{
    int stages = (K <= KC) ? 1 : 2;
    if (N >= 1024) {
        dim3 g(N / 128, M / 256, 1);
        hmma256_kernel<<<g, 256, 2 * STAGE256>>>(Ah, Al, Bh, Bl, bias, Chi, Clo,
            K, lda, ldb, ldh, flags);
    } else {
        dim3 g(N / 64, M / 128, nz);
        hmma_kernel<64><<<g, 256, stages * STAGE64>>>(Ah, Al, Bh, Bl, bias, Rb, Cf, Chi, Clo,
            K, lda, ldb, ldc, ldh, sAb, sAh, sBb, sBh, sCb, sCh, sHb, sHh, nh, flags);
    }
}

extern "C" void kernel_launch(void* const* d_in, const int* in_sizes, int n_in,
                              void* d_out, int out_size) {
    const float* word_emb = (const float*)d_in[0];
    const float* pos_emb  = (const float*)d_in[1];
    const float* emb_ln_g = (const float*)d_in[2];
    const float* emb_ln_b = (const float*)d_in[3];
    const float* rel_emb  = (const float*)d_in[4];
    const float* Wq = (const float*)d_in[5];
    const float* bq = (const float*)d_in[6];
    const float* Wk = (const float*)d_in[7];
    const float* bk = (const float*)d_in[8];
    const float* Wv = (const float*)d_in[9];
    const float* bv = (const float*)d_in[10];
    const float* Wo = (const float*)d_in[11];
    const float* bo = (const float*)d_in[12];
    const float* ln1_g = (const float*)d_in[13];
    const float* ln1_b = (const float*)d_in[14];
    const float* Wi = (const float*)d_in[15];
    const float* bi = (const float*)d_in[16];
    const float* Wo2 = (const float*)d_in[17];
    const float* bo2 = (const float*)d_in[18];
    const float* ln2_g = (const float*)d_in[19];
    const float* ln2_b = (const float*)d_in[20];
    const int* input_ids = (const int*)d_in[21];
    const int* attn_mask = (const int*)d_in[22];
    float* out = (float*)d_out;

    cudaFuncSetAttribute(hmma_kernel<64>, cudaFuncAttributeMaxDynamicSharedMemorySize, 2 * STAGE64);
    cudaFuncSetAttribute(hmma256_kernel,  cudaFuncAttributeMaxDynamicSharedMemorySize, 2 * STAGE256);

    float *x, *h1, *tmp, *sc, *c2p, *p2c, *p2cg, *qkvb;
    __nv_bfloat16 *xh, *xl, *h1h, *h1l, *qkvh, *qkvl, *ctxh, *ctxl;
    __nv_bfloat16 *ffh, *ffl, *pqkh, *pqkl, *relh, *rell, *wth, *wtl, *ph, *pl;
    cudaGetSymbolAddress((void**)&x, g_x);       cudaGetSymbolAddress((void**)&h1, g_h1);
    cudaGetSymbolAddress((void**)&tmp, g_tmp);
    cudaGetSymbolAddress((void**)&sc, g_sc);     cudaGetSymbolAddress((void**)&c2p, g_c2p);
    cudaGetSymbolAddress((void**)&p2c, g_p2c);   cudaGetSymbolAddress((void**)&p2cg, g_p2cg);
    cudaGetSymbolAddress((void**)&xh, g_xh);     cudaGetSymbolAddress((void**)&xl, g_xl);
    cudaGetSymbolAddress((void**)&h1h, g_h1h);   cudaGetSymbolAddress((void**)&h1l, g_h1l);
    cudaGetSymbolAddress((void**)&qkvh, g_qkvh); cudaGetSymbolAddress((void**)&qkvl, g_qkvl);
    cudaGetSymbolAddress((void**)&ctxh, g_ctxh); cudaGetSymbolAddress((void**)&ctxl, g_ctxl);
    cudaGetSymbolAddress((void**)&ffh, g_ffh);   cudaGetSymbolAddress((void**)&ffl, g_ffl);
    cudaGetSymbolAddress((void**)&pqkh, g_pqkh); cudaGetSymbolAddress((void**)&pqkl, g_pqkl);
    cudaGetSymbolAddress((void**)&relh, g_relh); cudaGetSymbolAddress((void**)&rell, g_rell);
    cudaGetSymbolAddress((void**)&wth, g_wth);   cudaGetSymbolAddress((void**)&wtl, g_wtl);
    cudaGetSymbolAddress((void**)&ph, g_ph);     cudaGetSymbolAddress((void**)&pl, g_pl);
    cudaGetSymbolAddress((void**)&qkvb, g_qkvb);

    __nv_bfloat16 *qh = qkvh,                      *ql = qkvl;
    __nv_bfloat16 *kh = qkvh + (size_t)ROWS * HID, *kl = qkvl + (size_t)ROWS * HID;
    __nv_bfloat16 *vth = qkvh + (size_t)2 * ROWS * HID, *vtl = qkvl + (size_t)2 * ROWS * HID;
    __nv_bfloat16 *pqh = pqkh,             *pql = pqkl;
    __nv_bfloat16 *pkh = pqkh + NHEAD * HD, *pkl = pqkl + NHEAD * HD;

    build_tables_kernel<<<1, 1024>>>();
    qkvbias_kernel<<<(NLAYER * 2304 + 255) / 256, 256>>>(bq, bk, bv, qkvb);

    dim3 tb(32, 8);
    wsplit_kernel<<<dim3(HID/32, HID/32, NLAYER), tb>>>(Wq,  wth + 0*WSZ,        wtl + 0*WSZ,        HID, HID,   (long long)WSZ,  (long long)LOFF);
    wsplit_kernel<<<dim3(HID/32, HID/32, NLAYER), tb>>>(Wk,  wth + 1*WSZ,        wtl + 1*WSZ,        HID, HID,   (long long)WSZ,  (long long)LOFF);
    wsplit_kernel<<<dim3(HID/32, HID/32, NLAYER), tb>>>(Wv,  wth + 2*WSZ,        wtl + 2*WSZ,        HID, HID,   (long long)WSZ,  (long long)LOFF);
    wsplit_kernel<<<dim3(HID/32, HID/32, NLAYER), tb>>>(Wo,  wth + 3*WSZ,        wtl + 3*WSZ,        HID, HID,   (long long)WSZ,  (long long)LOFF);
    wsplit_kernel<<<dim3(HID/32, FFDIM/32, NLAYER), tb>>>(Wi,  wth + 4*WSZ,      wtl + 4*WSZ,        HID, FFDIM, (long long)WISZ, (long long)LOFF);
    wsplit_kernel<<<dim3(FFDIM/32, HID/32, NLAYER), tb>>>(Wo2, wth + 4*WSZ+WISZ, wtl + 4*WSZ+WISZ,   FFDIM, HID, (long long)WISZ, (long long)LOFF);
    split_kernel<<<(SQ*HID + 255)/256, 256>>>(rel_emb, relh, rell, SQ*HID);

    embed_kernel<<<ROWS, 256>>>(word_emb, pos_emb, emb_ln_g, emb_ln_b, input_ids, attn_mask, x, xh, xl);

    const long long SS = (long long)SQ * SQ;
    const long long HSS = (long long)NHEAD * SS;
    const long long SHD = (long long)HD;
    const long long BHD = (long long)NHEAD * HD;

    for (int l = 0; l < NLAYER; l++) {
        const __nv_bfloat16 *WqTh = wth + (size_t)l*LOFF, *WqTl = wtl + (size_t)l*LOFF;
        const __nv_bfloat16 *WoTh = WqTh + 3*WSZ, *WoTl = WqTl + 3*WSZ;
        const __nv_bfloat16 *WiTh = WqTh + 4*WSZ, *WiTl = WqTl + 4*WSZ;
        const __nv_bfloat16 *W2Th = WqTh + 4*WSZ + WISZ, *W2Tl = WqTl + 4*WSZ + WISZ;
        const float *qkvb_l = qkvb + (size_t)l * 2304;
        const float *bo_l = bo + (size_t)l*HID, *bi_l = bi + (size_t)l*FFDIM, *bo2_l = bo2 + (size_t)l*HID;

        tmma(xh, xl, WqTh, WqTl, qkvb_l, nullptr, nullptr, qkvh, qkvl,
             ROWS, 2304, HID, HID, HID, 0, 0, 0,0,0,0, 0,0,0,0, 1, 1, FL_QKV);
        tmma(relh, rell, WqTh, WqTl, qkvb_l, nullptr, nullptr, pqkh, pqkl,
             SQ, 1536, HID, HID, HID, 0, 0, 0,0,0,0, 0,0,0,0, 1, 1, FL_PQK);

        tmma(qh, ql, kh, kl, nullptr, nullptr, sc, nullptr, nullptr,
             SQ, SQ, DHEAD, DHEAD, DHEAD, SQ, 0,
             BHD, SHD, BHD, SHD, HSS, SS, 0, 0, NHEAD, BHT, FL_F32);
        tmma(qh, ql, pkh, pkl, nullptr, nullptr, c2p, nullptr, nullptr,
             SQ, SQ, DHEAD, DHEAD, DHEAD, SQ, 0,
             BHD, SHD, 0, SHD, HSS, SS, 0, 0, NHEAD, BHT, FL_F32);
        tmma(kh, kl, pqh, pql, nullptr, nullptr, p2c, nullptr, nullptr,
             SQ, SQ, DHEAD, DHEAD, DHEAD, SQ, 0,
             BHD, SHD, 0, SHD, HSS, SS, 0, 0, NHEAD, BHT, FL_F32);

        p2cg_kernel<<<dim3(SQ/32, SQ/32, BHT), dim3(32, 8)>>>(p2c, p2cg);
        attn_softmax_kernel<<<dim3(SQ, BHT), 256>>>(sc, c2p, p2cg, attn_mask, ph, pl);

        tmma(ph, pl, vth, vtl, nullptr, nullptr, nullptr, ctxh, ctxl,
             SQ, DHEAD, SQ, SQ, SQ, 0, HID,
             HSS, SS, BHD, SHD, 0, 0, (long long)SQ*HID, DHEAD, NHEAD, BHT, FL_HILO);

        tmma(ctxh, ctxl, WoTh, WoTl, bo_l, x, tmp, nullptr, nullptr,
             ROWS, HID, HID, HID, HID, HID, 0, 0,0,0,0, 0,0,0,0, 1, 1, FL_F32 | FL_RES);
        ln_kernel<<<ROWS, 256>>>(tmp, ln1_g + (size_t)l*HID, ln1_b + (size_t)l*HID, h1, h1h, h1l);

        tmma(h1h, h1l, WiTh, WiTl, bi_l, nullptr, nullptr, ffh, ffl,
             ROWS, FFDIM, HID, HID, HID, 0, FFDIM, 0,0,0,0, 0,0,0,0, 1, 1, FL_GELU | FL_HILO);
        tmma(ffh, ffl, W2Th, W2Tl, bo2_l, h1, tmp, nullptr, nullptr,
             ROWS, HID, FFDIM, FFDIM, FFDIM, HID, 0, 0,0,0,0, 0,0,0,0, 1, 1, FL_F32 | FL_RES);
        ln_kernel<<<ROWS, 256>>>(tmp, ln2_g + (size_t)l*HID, ln2_b + (size_t)l*HID,
                                 (l == NLAYER - 1) ? out : x,
                                 (l == NLAYER - 1) ? nullptr : xh,
                                 (l == NLAYER - 1) ? nullptr : xl);
    }
}

// round 17
// speedup vs baseline: 1.1161x; 1.1161x over previous
#include <cuda_runtime.h>
#include <cuda_bf16.h>
#include <math.h>
#include <stdint.h>

#define SQ 512
#define HID 768
#define NHEAD 12
#define DHEAD 64
#define BATCH 8
#define NLAYER 12
#define FFDIM 3072
#define ROWS (BATCH*SQ)
#define BHT (BATCH*NHEAD)
#define HD (SQ*DHEAD)

#define WSZ (HID*HID)
#define WISZ (HID*FFDIM)
#define LOFF (4*WSZ + 2*WISZ)

/* ------------------------- scratch (device globals) ---------------------- */
__device__ float g_x[ROWS*HID];
__device__ float g_h1[ROWS*HID];
__device__ float g_tmp[ROWS*HID];
__device__ __nv_bfloat16 g_xh[ROWS*HID],  g_xl[ROWS*HID];
__device__ __nv_bfloat16 g_h1h[ROWS*HID], g_h1l[ROWS*HID];
__device__ __nv_bfloat16 g_qkvh[(size_t)3*ROWS*HID], g_qkvl[(size_t)3*ROWS*HID];
__device__ __nv_bfloat16 g_ctxh[ROWS*HID],g_ctxl[ROWS*HID];
__device__ __nv_bfloat16 g_ffh[(size_t)ROWS*FFDIM], g_ffl[(size_t)ROWS*FFDIM];
__device__ __nv_bfloat16 g_pqkh[2*NHEAD*HD], g_pqkl[2*NHEAD*HD];
__device__ __nv_bfloat16 g_relh[SQ*HID],  g_rell[SQ*HID];
__device__ __nv_bfloat16 g_wth[(size_t)NLAYER*LOFF];
__device__ __nv_bfloat16 g_wtl[(size_t)NLAYER*LOFF];
__device__ float g_qkvb[NLAYER*2304];
__device__ float g_sc[(size_t)BHT*SQ*SQ];
__device__ float g_c2p[(size_t)BHT*SQ*SQ];
__device__ float g_p2c[(size_t)BHT*SQ*SQ];
__device__ float g_p2cg[(size_t)BHT*SQ*SQ];
__device__ __nv_bfloat16 g_ph[(size_t)BHT*SQ*SQ], g_pl[(size_t)BHT*SQ*SQ];
__device__ int g_cidx[1023], g_pidx[1023];

/* ------------------------- PTX helpers ----------------------------------- */
__device__ __forceinline__ uint32_t smem_u32(const void* p) {
    uint32_t a;
    asm("{ .reg .u64 t; cvta.to.shared.u64 t, %1; cvt.u32.u64 %0, t; }" : "=r"(a) : "l"(p));
    return a;
}
#define SWZ(x) ((x) ^ (((x) >> 3) & 0x70))

#define CPA16(dst, src) asm volatile("cp.async.cg.shared.global [%0], [%1], 16;" :: "r"(dst), "l"(src))
#define CPA_COMMIT() asm volatile("cp.async.commit_group;" ::: "memory")
#define CPA_WAIT1() asm volatile("cp.async.wait_group 1;" ::: "memory")
#define CPA_WAIT0() asm volatile("cp.async.wait_group 0;" ::: "memory")

__device__ __forceinline__ void ldm4(uint32_t* r, uint32_t addr) {
    asm volatile("ldmatrix.sync.aligned.m8n8.x4.shared.b16 {%0,%1,%2,%3}, [%4];"
        : "=r"(r[0]), "=r"(r[1]), "=r"(r[2]), "=r"(r[3]) : "r"(addr));
}
__device__ __forceinline__ void mma16816(float* c, const uint32_t* a, uint32_t b0, uint32_t b1) {
    asm volatile("mma.sync.aligned.m16n8k16.row.col.f32.bf16.bf16.f32 "
        "{%0,%1,%2,%3}, {%4,%5,%6,%7}, {%8,%9}, {%0,%1,%2,%3};"
        : "+f"(c[0]), "+f"(c[1]), "+f"(c[2]), "+f"(c[3])
        : "r"(a[0]), "r"(a[1]), "r"(a[2]), "r"(a[3]), "r"(b0), "r"(b1));
}
__device__ __forceinline__ uint32_t amat_addr(uint32_t base, int mbase, int ks, int lane) {
    int mat = lane >> 3, rin = lane & 7;
    int m = mbase + rin + ((mat & 1) << 3);
    int quad = 2 * ks + (mat >> 1);
    return base + SWZ(m * 128 + quad * 16);
}
__device__ __forceinline__ uint32_t bmat_addr(uint32_t base, int nbase, int ks, int lane) {
    int mat = lane >> 3, rin = lane & 7;
    int n = nbase + rin + ((mat >> 1) << 3);
    int quad = 2 * ks + (mat & 1);
    return base + SWZ(n * 128 + quad * 16);
}

/* ------------------------- rel-pos bucket tables -------------------------- */
__device__ __forceinline__ int log_bucket(int rel) {
    const int mid = 128;
    float abs_pos;
    if (rel < mid && rel > -mid) abs_pos = (float)(mid - 1);
    else                         abs_pos = fabsf((float)rel);
    if (abs_pos <= (float)mid) return rel;
    float denom = (float)log(511.0 / 128.0);
    float log_pos = ceilf(logf(abs_pos / 128.0f) / denom * 127.0f) + 128.0f;
    float sgn = (rel > 0) ? 1.0f : ((rel < 0) ? -1.0f : 0.0f);
    return (int)(log_pos * sgn);
}
__global__ void build_tables_kernel() {
    int i = blockIdx.x * blockDim.x + threadIdx.x;
    if (i >= 1023) return;
    int d = i - 511;
    int c = log_bucket(d) + 256;  c = min(max(c, 0), 511);
    int p = 256 - log_bucket(-d); p = min(max(p, 0), 511);
    g_cidx[i] = c; g_pidx[i] = p;
}

__device__ __forceinline__ void split1(float v, __nv_bfloat16& h, __nv_bfloat16& l) {
    h = __float2bfloat16(v);
    l = __float2bfloat16(v - __bfloat162float(h));
}

/* staged concat bias [L][2304] = [bq|bk|bv] */
__global__ void qkvbias_kernel(const float* __restrict__ bq, const float* __restrict__ bk,
                               const float* __restrict__ bv, float* __restrict__ out) {
    int i = blockIdx.x * blockDim.x + threadIdx.x;
    if (i >= NLAYER * 2304) return;
    int l = i / 2304, j = i - l * 2304;
    float v;
    if (j < 768)       v = bq[l * 768 + j];
    else if (j < 1536) v = bk[l * 768 + j - 768];
    else               v = bv[l * 768 + j - 1536];
    out[i] = v;
}

/* transpose + hi/lo split: dst[n*K+k] = split(src[k*N+n]) */
__global__ void wsplit_kernel(const float* __restrict__ src, __nv_bfloat16* __restrict__ dh,
                              __nv_bfloat16* __restrict__ dl, int K, int N,
                              long long sStride, long long dStride) {
    __shared__ float t[32][33];
    int l = blockIdx.z;
    const float* s = src + (size_t)l * sStride;
    __nv_bfloat16* oh = dh + (size_t)l * dStride;
    __nv_bfloat16* ol = dl + (size_t)l * dStride;
    int k0 = blockIdx.x * 32, n0 = blockIdx.y * 32;
    int tx = threadIdx.x, ty = threadIdx.y;
#pragma unroll
    for (int i = 0; i < 32; i += 8) t[ty + i][tx] = s[(size_t)(k0 + ty + i) * N + n0 + tx];
    __syncthreads();
#pragma unroll
    for (int i = 0; i < 32; i += 8) {
        float v = t[tx][ty + i];
        __nv_bfloat16 h, lo; split1(v, h, lo);
        size_t o = (size_t)(n0 + ty + i) * K + k0 + tx;
        oh[o] = h; ol[o] = lo;
    }
}

__global__ void split_kernel(const float* __restrict__ s, __nv_bfloat16* __restrict__ oh,
                             __nv_bfloat16* __restrict__ ol, int n) {
    int i = blockIdx.x * blockDim.x + threadIdx.x;
    if (i < n) { __nv_bfloat16 h, l; split1(s[i], h, l); oh[i] = h; ol[i] = l; }
}

/* ------------------------- embedding + masked LN -------------------------- */
__global__ void embed_kernel(const float* __restrict__ we, const float* __restrict__ pe,
                             const float* __restrict__ lg, const float* __restrict__ lb,
                             const int* __restrict__ ids, const int* __restrict__ am,
                             float* __restrict__ out, __nv_bfloat16* __restrict__ outh,
                             __nv_bfloat16* __restrict__ outl) {
    __shared__ float red[256];
    int row = blockIdx.x, tid = threadIdx.x;
    int s = row & (SQ - 1);
    int id = ids[row];
    float v[3];
#pragma unroll
    for (int i = 0; i < 3; i++) {
        int c = tid + i * 256;
        v[i] = we[(size_t)id * HID + c] + pe[(size_t)s * HID + c];
    }
    float sum = v[0] + v[1] + v[2];
    red[tid] = sum; __syncthreads();
    for (int st = 128; st > 0; st >>= 1) { if (tid < st) red[tid] += red[tid + st]; __syncthreads(); }
    float mu = red[0] * (1.0f / HID); __syncthreads();
    float s2 = 0.f;
#pragma unroll
    for (int i = 0; i < 3; i++) { float d = v[i] - mu; s2 += d * d; }
    red[tid] = s2; __syncthreads();
    for (int st = 128; st > 0; st >>= 1) { if (tid < st) red[tid] += red[tid + st]; __syncthreads(); }
    float r = rsqrtf(red[0] * (1.0f / HID) + 1e-7f);
    float mf = (float)am[row];
    size_t rb = (size_t)row * HID;
#pragma unroll
    for (int i = 0; i < 3; i++) {
        int c = tid + i * 256;
        float o = ((v[i] - mu) * r * lg[c] + lb[c]) * mf;
        out[rb + c] = o;
        __nv_bfloat16 h, l; split1(o, h, l);
        outh[rb + c] = h; outl[rb + c] = l;
    }
}

/* ------------------------- layernorm (+ optional hi/lo) ------------------- */
__global__ void ln_kernel(const float* __restrict__ in, const float* __restrict__ lg,
                          const float* __restrict__ lb, float* __restrict__ out,
                          __nv_bfloat16* __restrict__ outh, __nv_bfloat16* __restrict__ outl) {
    __shared__ float red[256];
    int row = blockIdx.x, tid = threadIdx.x;
    const float* xr = in + (size_t)row * HID;
    float v[3];
#pragma unroll
    for (int i = 0; i < 3; i++) v[i] = xr[tid + i * 256];
    float sum = v[0] + v[1] + v[2];
    red[tid] = sum; __syncthreads();
    for (int st = 128; st > 0; st >>= 1) { if (tid < st) red[tid] += red[tid + st]; __syncthreads(); }
    float mu = red[0] * (1.0f / HID); __syncthreads();
    float s2 = 0.f;
#pragma unroll
    for (int i = 0; i < 3; i++) { float d = v[i] - mu; s2 += d * d; }
    red[tid] = s2; __syncthreads();
    for (int st = 128; st > 0; st >>= 1) { if (tid < st) red[tid] += red[tid + st]; __syncthreads(); }
    float r = rsqrtf(red[0] * (1.0f / HID) + 1e-7f);
    size_t rb = (size_t)row * HID;
#pragma unroll
    for (int i = 0; i < 3; i++) {
        int c = tid + i * 256;
        float o = (v[i] - mu) * r * lg[c] + lb[c];
        out[rb + c] = o;
        if (outh) { __nv_bfloat16 h, l; split1(o, h, l); outh[rb + c] = h; outl[rb + c] = l; }
    }
}

/* ------------------------- p2c transpose-gather --------------------------- */
__global__ void p2cg_kernel(const float* __restrict__ p2c, float* __restrict__ p2cg) {
    __shared__ float t[32][33];
    int bh = blockIdx.z;
    int k0 = blockIdx.x * 32, q0 = blockIdx.y * 32;
    const float* src = p2c + (size_t)bh * SQ * SQ;
    float* dst = p2cg + (size_t)bh * SQ * SQ;
    int tx = threadIdx.x, ty = threadIdx.y;
#pragma unroll
    for (int i = 0; i < 32; i += 8) {
        int k = k0 + ty + i;
        int q = q0 + tx;
        t[ty + i][tx] = src[(size_t)k * SQ + g_pidx[q - k + 511]];
    }
    __syncthreads();
#pragma unroll
    for (int i = 0; i < 32; i += 8)
        dst[(size_t)(q0 + ty + i) * SQ + k0 + tx] = t[tx][ty + i];
}

/* ------------------------- softmax (contiguous reads -> bf16 hi/lo) ------- */
__global__ void attn_softmax_kernel(const float* __restrict__ sc, const float* __restrict__ c2p,
                                    const float* __restrict__ p2cg, const int* __restrict__ am,
                                    __nv_bfloat16* __restrict__ ph, __nv_bfloat16* __restrict__ pl) {
    int q = blockIdx.x, bh = blockIdx.y;
    int b = bh / NHEAD;
    const float inv_scale = 0.07216878364870322f;
    const float* row  = sc   + ((size_t)bh * SQ + q) * SQ;
    const float* crow = c2p  + ((size_t)bh * SQ + q) * SQ;
    const float* prow = p2cg + ((size_t)bh * SQ + q) * SQ;
    int tid = threadIdx.x;
    bool mq = am[b * SQ + q] != 0;

    float v[2]; bool ok[2];
    float lmax = -3.402823466e38f;
#pragma unroll
    for (int i = 0; i < 2; i++) {
        int k = tid + i * 256;
        int di = q - k + 511;
        float s = (row[k] + crow[g_cidx[di]] + prow[k]) * inv_scale;
        ok[i] = mq && (am[b * SQ + k] != 0);
        v[i] = ok[i] ? s : -3.402823466e38f;
        lmax = fmaxf(lmax, v[i]);
    }
    __shared__ float red[256];
    red[tid] = lmax; __syncthreads();
    for (int st = 128; st > 0; st >>= 1) { if (tid < st) red[tid] = fmaxf(red[tid], red[tid + st]); __syncthreads(); }
    float m = red[0]; __syncthreads();
    float ls = 0.f;
#pragma unroll
    for (int i = 0; i < 2; i++) { float e = expf(v[i] - m); v[i] = e; ls += e; }
    red[tid] = ls; __syncthreads();
    for (int st = 128; st > 0; st >>= 1) { if (tid < st) red[tid] += red[tid + st]; __syncthreads(); }
    float inv = 1.0f / red[0];
    size_t ob = ((size_t)bh * SQ + q) * SQ;
#pragma unroll
    for (int i = 0; i < 2; i++) {
        int k = tid + i * 256;
        float p = ok[i] ? v[i] * inv : 0.0f;
        __nv_bfloat16 h, l; split1(p, h, l);
        ph[ob + k] = h; pl[ob + k] = l;
    }
}

/* ------------------------- mma.sync split-bf16 GEMM ----------------------- */
#define KC 64
#define ABYTES 16384

#define FL_GELU 1
#define FL_RES  2
#define FL_F32  4
#define FL_HILO 8
#define FL_QKV  64
#define FL_PQK  128

__device__ __forceinline__ void epi_pair(
    float v0, float v1, int m, int n,
    const float* bias, const float* Rb, float* Cf,
    __nv_bfloat16* Chi, __nv_bfloat16* Clo,
    int ldc, int ldh, size_t cfoff, size_t hoff, int flags)
{
    if (bias) { v0 += __ldg(bias + n); v1 += __ldg(bias + n + 1); }
    if (flags & FL_RES) {
        float2 rv = *reinterpret_cast<const float2*>(Rb + (size_t)m * ldc + n);
        v0 += rv.x; v1 += rv.y;
    }
    if (flags & FL_GELU) {
        v0 = 0.5f * v0 * (1.0f + erff(v0 * 0.70710678118654752f));
        v1 = 0.5f * v1 * (1.0f + erff(v1 * 0.70710678118654752f));
    }
    if (flags & FL_F32) {
        float2* p = reinterpret_cast<float2*>(Cf + cfoff + (size_t)m * ldc + n);
        *p = make_float2(v0, v1);
    }
    if (flags & FL_QKV) {
        int r = n / 768, nr = n - r * 768;
        __nv_bfloat16 h0, l0, h1, l1;
        split1(v0, h0, l0); split1(v1, h1, l1);
        if (r < 2) {
            size_t base = (size_t)r * ((size_t)ROWS * HID)
                        + (size_t)(m >> 9) * ((size_t)NHEAD * HD) + (size_t)(nr >> 6) * HD
                        + (size_t)(m & 511) * 64 + (nr & 63);
            __nv_bfloat162 hh; hh.x = h0; hh.y = h1;
            __nv_bfloat162 ll; ll.x = l0; ll.y = l1;
            *reinterpret_cast<uint32_t*>(Chi + base) = *reinterpret_cast<uint32_t*>(&hh);
            *reinterpret_cast<uint32_t*>(Clo + base) = *reinterpret_cast<uint32_t*>(&ll);
        } else {
            size_t vb = (size_t)2 * ((size_t)ROWS * HID);
            size_t i0 = vb + ((size_t)(m >> 9) * NHEAD + (nr >> 6)) * ((size_t)64 * SQ)
                      + (size_t)(nr & 63) * SQ + (m & 511);
            size_t i1 = vb + ((size_t)(m >> 9) * NHEAD + ((nr + 1) >> 6)) * ((size_t)64 * SQ)
                      + (size_t)((nr + 1) & 63) * SQ + (m & 511);
            Chi[i0] = h0; Clo[i0] = l0;
            Chi[i1] = h1; Clo[i1] = l1;
        }
        return;
    }
    if (flags & FL_PQK) {
        int r = n / 768, nr = n - r * 768;
        size_t base = (size_t)r * ((size_t)NHEAD * HD) + (size_t)(nr >> 6) * HD
                    + (size_t)m * 64 + (nr & 63);
        __nv_bfloat16 h0, l0, h1, l1;
        split1(v0, h0, l0); split1(v1, h1, l1);
        __nv_bfloat162 hh; hh.x = h0; hh.y = h1;
        __nv_bfloat162 ll; ll.x = l0; ll.y = l1;
        *reinterpret_cast<uint32_t*>(Chi + base) = *reinterpret_cast<uint32_t*>(&hh);
        *reinterpret_cast<uint32_t*>(Clo + base) = *reinterpret_cast<uint32_t*>(&ll);
        return;
    }
    if (flags & FL_HILO) {
        size_t base = hoff + (size_t)m * ldh + n;
        __nv_bfloat16 h0, l0, h1, l1;
        split1(v0, h0, l0); split1(v1, h1, l1);
        __nv_bfloat162 hh; hh.x = h0; hh.y = h1;
        __nv_bfloat162 ll; ll.x = l0; ll.y = l1;
        *reinterpret_cast<uint32_t*>(Chi + base) = *reinterpret_cast<uint32_t*>(&hh);
        *reinterpret_cast<uint32_t*>(Clo + base) = *reinterpret_cast<uint32_t*>(&ll);
    }
}

template<int TN>
__device__ __forceinline__ void load_chunk(
    uint32_t sst, const __nv_bfloat16* Azh, const __nv_bfloat16* Azl,
    const __nv_bfloat16* Bzh, const __nv_bfloat16* Bzl,
    int m0, int n0, int k0, int lda, int ldb, int tid)
{
    const uint32_t oAl = ABYTES, oBh = 2 * ABYTES, oBl = 2 * ABYTES + TN * 128;
#pragma unroll
    for (int i = 0; i < 4; i++) {
        int q = tid + i * 256;
        int row = q >> 3, quad = q & 7;
        size_t goff = (size_t)(m0 + row) * lda + k0 + quad * 8;
        uint32_t so = SWZ(row * 128 + quad * 16);
        CPA16(sst + so, Azh + goff);
        CPA16(sst + oAl + so, Azl + goff);
    }
#pragma unroll
    for (int i = 0; i < TN / 32; i++) {
        int q = tid + i * 256;
        int row = q >> 3, quad = q & 7;
        size_t goff = (size_t)(n0 + row) * ldb + k0 + quad * 8;
        uint32_t so = SWZ(row * 128 + quad * 16);
        CPA16(sst + oBh + so, Bzh + goff);
        CPA16(sst + oBl + so, Bzl + goff);
    }
    CPA_COMMIT();
}

template<int TN>
__global__ __launch_bounds__(256, (TN == 64) ? 2 : 1)
void hmma_kernel(const __nv_bfloat16* __restrict__ Ah, const __nv_bfloat16* __restrict__ Al,
                 const __nv_bfloat16* __restrict__ Bh, const __nv_bfloat16* __restrict__ Bl,
                 const float* __restrict__ bias, const float* __restrict__ Rb,
                 float* __restrict__ Cf, __nv_bfloat16* __restrict__ Chi, __nv_bfloat16* __restrict__ Clo,
                 int K, int lda, int ldb, int ldc, int ldh,
                 long long sAb, long long sAh_, long long sBb, long long sBh_,
                 long long sCb, long long sCh_, long long sHb, long long sHh_,
                 int nh, int flags)
{
    extern __shared__ char smem[];
    const int STAGE = 2 * ABYTES + 2 * TN * 128;
    uint32_t sb = smem_u32(smem);

    int tid = threadIdx.x, wid = tid >> 5, lane = tid & 31;
    int z = blockIdx.z, bo = z / nh, ho = z - bo * nh;
    int m0 = blockIdx.y * 128, n0 = blockIdx.x * TN;

    const __nv_bfloat16* Azh = Ah + (size_t)bo * sAb + (size_t)ho * sAh_;
    const __nv_bfloat16* Azl = Al + (size_t)bo * sAb + (size_t)ho * sAh_;
    const __nv_bfloat16* Bzh = Bh + (size_t)bo * sBb + (size_t)ho * sBh_;
    const __nv_bfloat16* Bzl = Bl + (size_t)bo * sBb + (size_t)ho * sBh_;

    const int MI = (TN == 128) ? 2 : 1;
    int wm = (TN == 128) ? (wid & 3) * 32 : wid * 16;
    int wn = (TN == 128) ? (wid >> 2) * 64 : 0;

    float acc[(TN == 128) ? 2 : 1][8][4];
#pragma unroll
    for (int a = 0; a < MI; a++)
#pragma unroll
        for (int b = 0; b < 8; b++)
#pragma unroll
            for (int c = 0; c < 4; c++) acc[a][b][c] = 0.f;

    int nch = K / KC;
    load_chunk<TN>(sb, Azh, Azl, Bzh, Bzl, m0, n0, 0, lda, ldb, tid);

    for (int ch = 0; ch < nch; ch++) {
        if (ch + 1 < nch) {
            load_chunk<TN>(sb + ((ch + 1) & 1) * STAGE, Azh, Azl, Bzh, Bzl,
                           m0, n0, (ch + 1) * KC, lda, ldb, tid);
            CPA_WAIT1();
        } else {
            CPA_WAIT0();
        }
        __syncthreads();

        uint32_t st = sb + (ch & 1) * STAGE;
        const uint32_t oAl = ABYTES, oBh = 2 * ABYTES, oBl = 2 * ABYTES + TN * 128;
#pragma unroll
        for (int ks = 0; ks < 4; ks++) {
            uint32_t ah[MI][4], al[MI][4];
#pragma unroll
            for (int mi = 0; mi < MI; mi++) {
                ldm4(ah[mi], amat_addr(st, wm + mi * 16, ks, lane));
                ldm4(al[mi], amat_addr(st + oAl, wm + mi * 16, ks, lane));
            }
#pragma unroll
            for (int ngp = 0; ngp < 4; ngp += 2) {
                uint32_t b0h[4], b1h[4], b0l[4], b1l[4];
                ldm4(b0h, bmat_addr(st + oBh, wn + ngp * 16, ks, lane));
                ldm4(b1h, bmat_addr(st + oBh, wn + (ngp + 1) * 16, ks, lane));
                ldm4(b0l, bmat_addr(st + oBl, wn + ngp * 16, ks, lane));
                ldm4(b1l, bmat_addr(st + oBl, wn + (ngp + 1) * 16, ks, lane));
#pragma unroll
                for (int mi = 0; mi < MI; mi++) {
                    mma16816(acc[mi][2 * ngp],     ah[mi], b0h[0], b0h[1]);
                    mma16816(acc[mi][2 * ngp + 1], ah[mi], b0h[2], b0h[3]);
                    mma16816(acc[mi][2 * ngp + 2], ah[mi], b1h[0], b1h[1]);
                    mma16816(acc[mi][2 * ngp + 3], ah[mi], b1h[2], b1h[3]);
                }
#pragma unroll
                for (int mi = 0; mi < MI; mi++) {
                    mma16816(acc[mi][2 * ngp],     ah[mi], b0l[0], b0l[1]);
                    mma16816(acc[mi][2 * ngp + 1], ah[mi], b0l[2], b0l[3]);
                    mma16816(acc[mi][2 * ngp + 2], ah[mi], b1l[0], b1l[1]);
                    mma16816(acc[mi][2 * ngp + 3], ah[mi], b1l[2], b1l[3]);
                }
#pragma unroll
                for (int mi = 0; mi < MI; mi++) {
                    mma16816(acc[mi][2 * ngp],     al[mi], b0h[0], b0h[1]);
                    mma16816(acc[mi][2 * ngp + 1], al[mi], b0h[2], b0h[3]);
                    mma16816(acc[mi][2 * ngp + 2], al[mi], b1h[0], b1h[1]);
                    mma16816(acc[mi][2 * ngp + 3], al[mi], b1h[2], b1h[3]);
                }
            }
        }
        __syncthreads();
    }

    size_t cfoff = (size_t)bo * sCb + (size_t)ho * sCh_;
    size_t hoff  = (size_t)bo * sHb + (size_t)ho * sHh_;
    int r0 = lane >> 2, cc = (lane & 3) * 2;
#pragma unroll
    for (int mi = 0; mi < MI; mi++) {
#pragma unroll
        for (int nf = 0; nf < 8; nf++) {
            int m_ = m0 + wm + mi * 16 + r0;
            int n_ = n0 + wn + nf * 8 + cc;
            epi_pair(acc[mi][nf][0], acc[mi][nf][1], m_,     n_, bias, Rb, Cf, Chi, Clo, ldc, ldh, cfoff, hoff, flags);
            epi_pair(acc[mi][nf][2], acc[mi][nf][3], m_ + 8, n_, bias, Rb, Cf, Chi, Clo, ldc, ldh, cfoff, hoff, flags);
        }
    }
}

/* ------------------------- host-side GEMM wrapper ------------------------- */
#define STAGE128 (2 * ABYTES + 2 * 128 * 128)
#define STAGE64  (2 * ABYTES + 2 * 64 * 128)

static void tmma(const __nv_bfloat16* Ah, const __nv_bfloat16* Al,
                 const __nv_bfloat16* Bh, const __nv_bfloat16* Bl,
                 const float* bias, const float* Rb,
                 float* Cf, __nv_bfloat16* Chi, __nv_bfloat16* Clo,
                 int M, int N, int K, int lda, int ldb, int ldc, int ldh,
                 long long sAb, long long sAh, long long sBb, long long sBh,
                 long long sCb, long long sCh, long long sHb, long long sHh,
                 int nh, int nz, int flags)
{
    int stages = (K <= KC) ? 1 : 2;
    if (N >= 1024) {
        dim3 g(N / 128, M / 128, nz);
        hmma_kernel<128><<<g, 256, stages * STAGE128>>>(Ah, Al, Bh, Bl, bias, Rb, Cf, Chi, Clo,
            K, lda, ldb, ldc, ldh, sAb, sAh, sBb, sBh, sCb, sCh, sHb, sHh, nh, flags);
    } else {
        dim3 g(N / 64, M / 128, nz);
        hmma_kernel<64><<<g, 256, stages * STAGE64>>>(Ah, Al, Bh, Bl, bias, Rb, Cf, Chi, Clo,
            K, lda, ldb, ldc, ldh, sAb, sAh, sBb, sBh, sCb, sCh, sHb, sHh, nh, flags);
    }
}

extern "C" void kernel_launch(void* const* d_in, const int* in_sizes, int n_in,
                              void* d_out, int out_size) {
    const float* word_emb = (const float*)d_in[0];
    const float* pos_emb  = (const float*)d_in[1];
    const float* emb_ln_g = (const float*)d_in[2];
    const float* emb_ln_b = (const float*)d_in[3];
    const float* rel_emb  = (const float*)d_in[4];
    const float* Wq = (const float*)d_in[5];
    const float* bq = (const float*)d_in[6];
    const float* Wk = (const float*)d_in[7];
    const float* bk = (const float*)d_in[8];
    const float* Wv = (const float*)d_in[9];
    const float* bv = (const float*)d_in[10];
    const float* Wo = (const float*)d_in[11];
    const float* bo = (const float*)d_in[12];
    const float* ln1_g = (const float*)d_in[13];
    const float* ln1_b = (const float*)d_in[14];
    const float* Wi = (const float*)d_in[15];
    const float* bi = (const float*)d_in[16];
    const float* Wo2 = (const float*)d_in[17];
    const float* bo2 = (const float*)d_in[18];
    const float* ln2_g = (const float*)d_in[19];
    const float* ln2_b = (const float*)d_in[20];
    const int* input_ids = (const int*)d_in[21];
    const int* attn_mask = (const int*)d_in[22];
    float* out = (float*)d_out;

    cudaFuncSetAttribute(hmma_kernel<128>, cudaFuncAttributeMaxDynamicSharedMemorySize, 2 * STAGE128);
    cudaFuncSetAttribute(hmma_kernel<64>,  cudaFuncAttributeMaxDynamicSharedMemorySize, 2 * STAGE64);

    float *x, *h1, *tmp, *sc, *c2p, *p2c, *p2cg, *qkvb;
    __nv_bfloat16 *xh, *xl, *h1h, *h1l, *qkvh, *qkvl, *ctxh, *ctxl;
    __nv_bfloat16 *ffh, *ffl, *pqkh, *pqkl, *relh, *rell, *wth, *wtl, *ph, *pl;
    cudaGetSymbolAddress((void**)&x, g_x);       cudaGetSymbolAddress((void**)&h1, g_h1);
    cudaGetSymbolAddress((void**)&tmp, g_tmp);
    cudaGetSymbolAddress((void**)&sc, g_sc);     cudaGetSymbolAddress((void**)&c2p, g_c2p);
    cudaGetSymbolAddress((void**)&p2c, g_p2c);   cudaGetSymbolAddress((void**)&p2cg, g_p2cg);
    cudaGetSymbolAddress((void**)&xh, g_xh);     cudaGetSymbolAddress((void**)&xl, g_xl);
    cudaGetSymbolAddress((void**)&h1h, g_h1h);   cudaGetSymbolAddress((void**)&h1l, g_h1l);
    cudaGetSymbolAddress((void**)&qkvh, g_qkvh); cudaGetSymbolAddress((void**)&qkvl, g_qkvl);
    cudaGetSymbolAddress((void**)&ctxh, g_ctxh); cudaGetSymbolAddress((void**)&ctxl, g_ctxl);
    cudaGetSymbolAddress((void**)&ffh, g_ffh);   cudaGetSymbolAddress((void**)&ffl, g_ffl);
    cudaGetSymbolAddress((void**)&pqkh, g_pqkh); cudaGetSymbolAddress((void**)&pqkl, g_pqkl);
    cudaGetSymbolAddress((void**)&relh, g_relh); cudaGetSymbolAddress((void**)&rell, g_rell);
    cudaGetSymbolAddress((void**)&wth, g_wth);   cudaGetSymbolAddress((void**)&wtl, g_wtl);
    cudaGetSymbolAddress((void**)&ph, g_ph);     cudaGetSymbolAddress((void**)&pl, g_pl);
    cudaGetSymbolAddress((void**)&qkvb, g_qkvb);

    __nv_bfloat16 *qh = qkvh,                      *ql = qkvl;
    __nv_bfloat16 *kh = qkvh + (size_t)ROWS * HID, *kl = qkvl + (size_t)ROWS * HID;
    __nv_bfloat16 *vth = qkvh + (size_t)2 * ROWS * HID, *vtl = qkvl + (size_t)2 * ROWS * HID;
    __nv_bfloat16 *pqh = pqkh,             *pql = pqkl;
    __nv_bfloat16 *pkh = pqkh + NHEAD * HD, *pkl = pqkl + NHEAD * HD;

    build_tables_kernel<<<1, 1024>>>();
    qkvbias_kernel<<<(NLAYER * 2304 + 255) / 256, 256>>>(bq, bk, bv, qkvb);

    dim3 tb(32, 8);
    wsplit_kernel<<<dim3(HID/32, HID/32, NLAYER), tb>>>(Wq,  wth + 0*WSZ,        wtl + 0*WSZ,        HID, HID,   (long long)WSZ,  (long long)LOFF);
    wsplit_kernel<<<dim3(HID/32, HID/32, NLAYER), tb>>>(Wk,  wth + 1*WSZ,        wtl + 1*WSZ,        HID, HID,   (long long)WSZ,  (long long)LOFF);
    wsplit_kernel<<<dim3(HID/32, HID/32, NLAYER), tb>>>(Wv,  wth + 2*WSZ,        wtl + 2*WSZ,        HID, HID,   (long long)WSZ,  (long long)LOFF);
    wsplit_kernel<<<dim3(HID/32, HID/32, NLAYER), tb>>>(Wo,  wth + 3*WSZ,        wtl + 3*WSZ,        HID, HID,   (long long)WSZ,  (long long)LOFF);
    wsplit_kernel<<<dim3(HID/32, FFDIM/32, NLAYER), tb>>>(Wi,  wth + 4*WSZ,      wtl + 4*WSZ,        HID, FFDIM, (long long)WISZ, (long long)LOFF);
    wsplit_kernel<<<dim3(FFDIM/32, HID/32, NLAYER), tb>>>(Wo2, wth + 4*WSZ+WISZ, wtl + 4*WSZ+WISZ,   FFDIM, HID, (long long)WISZ, (long long)LOFF);
    split_kernel<<<(SQ*HID + 255)/256, 256>>>(rel_emb, relh, rell, SQ*HID);

    embed_kernel<<<ROWS, 256>>>(word_emb, pos_emb, emb_ln_g, emb_ln_b, input_ids, attn_mask, x, xh, xl);

    const long long SS = (long long)SQ * SQ;
    const long long HSS = (long long)NHEAD * SS;
    const long long SHD = (long long)HD;
    const long long BHD = (long long)NHEAD * HD;

    for (int l = 0; l < NLAYER; l++) {
        const __nv_bfloat16 *WqTh = wth + (size_t)l*LOFF, *WqTl = wtl + (size_t)l*LOFF;
        const __nv_bfloat16 *WoTh = WqTh + 3*WSZ, *WoTl = WqTl + 3*WSZ;
        const __nv_bfloat16 *WiTh = WqTh + 4*WSZ, *WiTl = WqTl + 4*WSZ;
        const __nv_bfloat16 *W2Th = WqTh + 4*WSZ + WISZ, *W2Tl = WqTl + 4*WSZ + WISZ;
        const float *qkvb_l = qkvb + (size_t)l * 2304;
        const float *bo_l = bo + (size_t)l*HID, *bi_l = bi + (size_t)l*FFDIM, *bo2_l = bo2 + (size_t)l*HID;

        tmma(xh, xl, WqTh, WqTl, qkvb_l, nullptr, nullptr, qkvh, qkvl,
             ROWS, 2304, HID, HID, HID, 0, 0, 0,0,0,0, 0,0,0,0, 1, 1, FL_QKV);
        tmma(relh, rell, WqTh, WqTl, qkvb_l, nullptr, nullptr, pqkh, pqkl,
             SQ, 1536, HID, HID, HID, 0, 0, 0,0,0,0, 0,0,0,0, 1, 1, FL_PQK);

        tmma(qh, ql, kh, kl, nullptr, nullptr, sc, nullptr, nullptr,
             SQ, SQ, DHEAD, DHEAD, DHEAD, SQ, 0,
             BHD, SHD, BHD, SHD, HSS, SS, 0, 0, NHEAD, BHT, FL_F32);
        tmma(qh, ql, pkh, pkl, nullptr, nullptr, c2p, nullptr, nullptr,
             SQ, SQ, DHEAD, DHEAD, DHEAD, SQ, 0,
             BHD, SHD, 0, SHD, HSS, SS, 0, 0, NHEAD, BHT, FL_F32);
        tmma(kh, kl, pqh, pql, nullptr, nullptr, p2c, nullptr, nullptr,
             SQ, SQ, DHEAD, DHEAD, DHEAD, SQ, 0,
             BHD, SHD, 0, SHD, HSS, SS, 0, 0, NHEAD, BHT, FL_F32);

        p2cg_kernel<<<dim3(SQ/32, SQ/32, BHT), dim3(32, 8)>>>(p2c, p2cg);
        attn_softmax_kernel<<<dim3(SQ, BHT), 256>>>(sc, c2p, p2cg, attn_mask, ph, pl);

        tmma(ph, pl, vth, vtl, nullptr, nullptr, nullptr, ctxh, ctxl,
             SQ, DHEAD, SQ, SQ, SQ, 0, HID,
             HSS, SS, BHD, SHD, 0, 0, (long long)SQ*HID, DHEAD, NHEAD, BHT, FL_HILO);

        tmma(ctxh, ctxl, WoTh, WoTl, bo_l, x, tmp, nullptr, nullptr,
             ROWS, HID, HID, HID, HID, HID, 0, 0,0,0,0, 0,0,0,0, 1, 1, FL_F32 | FL_RES);
        ln_kernel<<<ROWS, 256>>>(tmp, ln1_g + (size_t)l*HID, ln1_b + (size_t)l*HID, h1, h1h, h1l);

        tmma(h1h, h1l, WiTh, WiTl, bi_l, nullptr, nullptr, ffh, ffl,
             ROWS, FFDIM, HID, HID, HID, 0, FFDIM, 0,0,0,0, 0,0,0,0, 1, 1, FL_GELU | FL_HILO);
        tmma(ffh, ffl, W2Th, W2Tl, bo2_l, h1, tmp, nullptr, nullptr,
             ROWS, HID, FFDIM, FFDIM, FFDIM, HID, 0, 0,0,0,0, 0,0,0,0, 1, 1, FL_F32 | FL_RES);
        ln_kernel<<<ROWS, 256>>>(tmp, ln2_g + (size_t)l*HID, ln2_b + (size_t)l*HID,
                                 (l == NLAYER - 1) ? out : x,
                                 (l == NLAYER - 1) ? nullptr : xh,
                                 (l == NLAYER - 1) ? nullptr : xl);
    }
}